// round 16
// baseline (speedup 1.0000x reference)
#include <cuda_runtime.h>

#define NB   2048
#define ND   128
#define TILE 64          // output tile edge
#define KCH  32          // dims per pipeline stage
#define NCH  (ND / KCH)

// exponent constants, pre-scaled by log2(e) for ex2.approx
#define K_MIN  18.755035531556525f    //  13.0 * log2(e)
#define K_ABS  -9.3775177657782625f   //  -6.5 * log2(e)

// Scratch
__device__ float g_XT[ND * NB];   // attn-scaled (x0.5 on d%4==3), transposed
__device__ float g_ET[ND * NB];
__device__ float g_P[NB];         // K_ABS * sum over d%4!=3 of attn*x
__device__ float g_Q[NB];

__device__ __forceinline__ void cp16(unsigned smem_addr, const void* gptr) {
    asm volatile("cp.async.ca.shared.global [%0], [%1], 16;\n"
                 :: "r"(smem_addr), "l"(gptr));
}
__device__ __forceinline__ void cp_commit() {
    asm volatile("cp.async.commit_group;\n");
}
template<int N>
__device__ __forceinline__ void cp_wait() {
    asm volatile("cp.async.wait_group %0;\n" :: "n"(N));
}
__device__ __forceinline__ float ex2(float x) {
    float r; asm("ex2.approx.f32 %0, %1;" : "=f"(r) : "f"(x)); return r;
}

// ---------------------------------------------------------------------------
// Prep: transpose + attn-scale + partial rowsum (d%4 != 3), log2e-scaled.
// d%4==3 dims additionally scaled by 0.5 so the main kernel folds the abs
// route into the SAME accumulator as the min route.
// ---------------------------------------------------------------------------
__global__ __launch_bounds__(256) void prep2_kernel(
    const float* __restrict__ X, const float* __restrict__ E,
    const float* __restrict__ attn)
{
    __shared__ float a[ND];
    __shared__ float T[32][ND + 1];

    int bid = blockIdx.x;
    bool isE = bid >= 64;
    const float* src = isE ? E : X;
    float* dstT      = isE ? g_ET : g_XT;
    float* sums      = isE ? g_Q  : g_P;
    int rowbase = (bid & 63) * 32;

    int t = threadIdx.x;
    if (t < ND) a[t] = attn[t] * ((t & 3) == 3 ? 0.5f : 1.0f);
    __syncthreads();

    int r   = t >> 3;
    int seg = t & 7;
    const float4* srow = (const float4*)&src[(rowbase + r) * ND + seg * 16];
    float s = 0.0f;
    #pragma unroll
    for (int k = 0; k < 4; k++) {
        float4 v = srow[k];
        int d = seg * 16 + k * 4;
        v.x *= a[d + 0]; v.y *= a[d + 1]; v.z *= a[d + 2]; v.w *= a[d + 3];
        T[r][d + 0] = v.x; T[r][d + 1] = v.y;
        T[r][d + 2] = v.z; T[r][d + 3] = v.w;
        s += v.x + v.y + v.z;          // skip v.w: d%4==3 -> abs route
    }
    s += __shfl_down_sync(0xffffffffu, s, 4);
    s += __shfl_down_sync(0xffffffffu, s, 2);
    s += __shfl_down_sync(0xffffffffu, s, 1);
    if (seg == 0) sums[rowbase + r] = K_ABS * s;
    __syncthreads();

    #pragma unroll
    for (int k = 0; k < 4; k++) {
        int o  = t + k * 256;
        int d  = o >> 3;
        int rg = o & 7;
        float4 v;
        v.x = T[rg * 4 + 0][d];
        v.y = T[rg * 4 + 1][d];
        v.z = T[rg * 4 + 2][d];
        v.w = T[rg * 4 + 3][d];
        *(float4*)&dstT[d * NB + rowbase + rg * 4] = v;
    }
}

// ---------------------------------------------------------------------------
// Main: 64x64 tile, 256 threads, 4x4 micro-tile, cp.async double buffer,
// merged accumulator, 6 blocks/SM (reg cap 40):
//   d%4 != 3 : acc += min(u,v)      (FMNMX alu + FADD fma)
//   d%4 == 3 : acc -= |u' - v'|     (FADD + FADD.neg-abs, fma pipe)
// out = ex2(P + Q + K_MIN*acc)
// ---------------------------------------------------------------------------
__global__ __launch_bounds__(256, 6) void alcove_main(float* __restrict__ out)
{
    __shared__ float Xs[2][KCH * TILE];   // 2 x 8KB
    __shared__ float Es[2][KCH * TILE];   // 2 x 8KB

    int tid = threadIdx.x;
    int tx  = tid & 15;
    int ty  = tid >> 4;
    int rb  = blockIdx.y * TILE;
    int cb  = blockIdx.x * TILE;

    float acc[4][4];
    #pragma unroll
    for (int i = 0; i < 4; i++)
        #pragma unroll
        for (int j = 0; j < 4; j++) acc[i][j] = 0.0f;

    int fi0 = tid, fi1 = tid + 256;
    int d0 = fi0 >> 4, q0i = fi0 & 15;
    int d1 = fi1 >> 4, q1i = fi1 & 15;

    const float4* gx = (const float4*)g_XT;
    const float4* ge = (const float4*)g_ET;

    unsigned sx0 = (unsigned)__cvta_generic_to_shared(&Xs[0][0]);
    unsigned se0 = (unsigned)__cvta_generic_to_shared(&Es[0][0]);

    auto issue_stage = [&](int kb, int buf) {
        int base = kb * KCH;
        unsigned xb = sx0 + buf * (KCH * TILE * 4);
        unsigned eb = se0 + buf * (KCH * TILE * 4);
        cp16(xb + (d0 * 16 + q0i) * 16, &gx[(base + d0) * (NB/4) + (rb>>2) + q0i]);
        cp16(xb + (d1 * 16 + q1i) * 16, &gx[(base + d1) * (NB/4) + (rb>>2) + q1i]);
        cp16(eb + (d0 * 16 + q0i) * 16, &ge[(base + d0) * (NB/4) + (cb>>2) + q0i]);
        cp16(eb + (d1 * 16 + q1i) * 16, &ge[(base + d1) * (NB/4) + (cb>>2) + q1i]);
        cp_commit();
    };

    issue_stage(0, 0);

    #pragma unroll 1
    for (int kb = 0; kb < NCH; kb++) {
        int buf = kb & 1;
        cp_wait<0>();          // stage kb data landed
        __syncthreads();       // all warps finished reading buf^1
        if (kb + 1 < NCH)
            issue_stage(kb + 1, buf ^ 1);   // overlaps with compute below

        const float* Xb = &Xs[buf][ty * 4];
        const float* Eb = &Es[buf][tx * 4];
        #pragma unroll
        for (int d4 = 0; d4 < KCH; d4 += 4) {
            #pragma unroll
            for (int dd = 0; dd < 3; dd++) {
                float4 xv = *(const float4*)&Xb[(d4 + dd) * TILE];
                float4 ev = *(const float4*)&Eb[(d4 + dd) * TILE];
                float x[4] = {xv.x, xv.y, xv.z, xv.w};
                #pragma unroll
                for (int i = 0; i < 4; i++) {
                    acc[i][0] += fminf(x[i], ev.x);
                    acc[i][1] += fminf(x[i], ev.y);
                    acc[i][2] += fminf(x[i], ev.z);
                    acc[i][3] += fminf(x[i], ev.w);
                }
            }
            {
                float4 xv = *(const float4*)&Xb[(d4 + 3) * TILE];
                float4 ev = *(const float4*)&Eb[(d4 + 3) * TILE];
                float x[4] = {xv.x, xv.y, xv.z, xv.w};
                #pragma unroll
                for (int i = 0; i < 4; i++) {
                    acc[i][0] -= fabsf(x[i] - ev.x);
                    acc[i][1] -= fabsf(x[i] - ev.y);
                    acc[i][2] -= fabsf(x[i] - ev.z);
                    acc[i][3] -= fabsf(x[i] - ev.w);
                }
            }
        }
    }

    // Epilogue: out = ex2(p + q + K_MIN*acc)
    float q0 = g_Q[cb + tx * 4 + 0];
    float q1 = g_Q[cb + tx * 4 + 1];
    float q2 = g_Q[cb + tx * 4 + 2];
    float q3 = g_Q[cb + tx * 4 + 3];
    #pragma unroll
    for (int i = 0; i < 4; i++) {
        int r = rb + ty * 4 + i;
        float p = g_P[r];
        float4 o;
        o.x = ex2(fmaf(K_MIN, acc[i][0], p + q0));
        o.y = ex2(fmaf(K_MIN, acc[i][1], p + q1));
        o.z = ex2(fmaf(K_MIN, acc[i][2], p + q2));
        o.w = ex2(fmaf(K_MIN, acc[i][3], p + q3));
        *(float4*)&out[r * NB + cb + tx * 4] = o;
    }
}

// ---------------------------------------------------------------------------
extern "C" void kernel_launch(void* const* d_in, const int* in_sizes, int n_in,
                              void* d_out, int out_size)
{
    const float* inputs    = (const float*)d_in[0];
    const float* exemplars = (const float*)d_in[1];
    const float* attn      = (const float*)d_in[2];
    float* out = (float*)d_out;

    prep2_kernel<<<128, 256>>>(inputs, exemplars, attn);

    dim3 grid(NB / TILE, NB / TILE);   // 32 x 32 = 1024 tiles
    alcove_main<<<grid, 256>>>(out);
}

// round 17
// speedup vs baseline: 1.0447x; 1.0447x over previous
#include <cuda_runtime.h>

#define NB   2048
#define ND   128
#define TILE 64          // output tile edge
#define KCH  32          // dims per pipeline stage
#define NCH  (ND / KCH)

// exponent constants, pre-scaled by log2(e) for ex2.approx
#define K_MIN  18.755035531556525f    //  13.0 * log2(e)
#define K_ABS  -9.3775177657782625f   //  -6.5 * log2(e)

// abs-route dims: d % 8 in {2,5,7}  (5 min : 3 abs per 8 -> pipe balance)
// Scratch
__device__ float g_XT[ND * NB];   // attn-scaled (x0.5 on abs dims), transposed
__device__ float g_ET[ND * NB];
__device__ float g_P[NB];         // K_ABS * sum over min-dims of attn*x
__device__ float g_Q[NB];

__device__ __forceinline__ void cp16(unsigned smem_addr, const void* gptr) {
    asm volatile("cp.async.ca.shared.global [%0], [%1], 16;\n"
                 :: "r"(smem_addr), "l"(gptr));
}
__device__ __forceinline__ void cp_commit() {
    asm volatile("cp.async.commit_group;\n");
}
template<int N>
__device__ __forceinline__ void cp_wait() {
    asm volatile("cp.async.wait_group %0;\n" :: "n"(N));
}
__device__ __forceinline__ float ex2(float x) {
    float r; asm("ex2.approx.f32 %0, %1;" : "=f"(r) : "f"(x)); return r;
}

// ---------------------------------------------------------------------------
// Prep: transpose + attn-scale + partial rowsum over min-dims, log2e-scaled.
// Abs dims (d%8 in {2,5,7}) scaled by extra 0.5 so the main kernel folds the
// abs route into the SAME accumulator as the min route.
// ---------------------------------------------------------------------------
__global__ __launch_bounds__(256) void prep2_kernel(
    const float* __restrict__ X, const float* __restrict__ E,
    const float* __restrict__ attn)
{
    __shared__ float a[ND];
    __shared__ float T[32][ND + 1];

    int bid = blockIdx.x;
    bool isE = bid >= 64;
    const float* src = isE ? E : X;
    float* dstT      = isE ? g_ET : g_XT;
    float* sums      = isE ? g_Q  : g_P;
    int rowbase = (bid & 63) * 32;

    int t = threadIdx.x;
    if (t < ND) {
        int m = t & 7;
        bool isAbs = (m == 2) | (m == 5) | (m == 7);
        a[t] = attn[t] * (isAbs ? 0.5f : 1.0f);
    }
    __syncthreads();

    int r   = t >> 3;
    int seg = t & 7;
    const float4* srow = (const float4*)&src[(rowbase + r) * ND + seg * 16];
    float s = 0.0f;
    #pragma unroll
    for (int k = 0; k < 4; k++) {
        float4 v = srow[k];
        int d = seg * 16 + k * 4;       // d % 8 == (k*4) % 8
        v.x *= a[d + 0]; v.y *= a[d + 1]; v.z *= a[d + 2]; v.w *= a[d + 3];
        T[r][d + 0] = v.x; T[r][d + 1] = v.y;
        T[r][d + 2] = v.z; T[r][d + 3] = v.w;
        if ((k & 1) == 0) s += v.x + v.y + v.w;   // abs at c=2 (d%8==2)
        else              s += v.x + v.z;         // abs at c=1,3 (d%8==5,7)
    }
    s += __shfl_down_sync(0xffffffffu, s, 4);
    s += __shfl_down_sync(0xffffffffu, s, 2);
    s += __shfl_down_sync(0xffffffffu, s, 1);
    if (seg == 0) sums[rowbase + r] = K_ABS * s;
    __syncthreads();

    #pragma unroll
    for (int k = 0; k < 4; k++) {
        int o  = t + k * 256;
        int d  = o >> 3;
        int rg = o & 7;
        float4 v;
        v.x = T[rg * 4 + 0][d];
        v.y = T[rg * 4 + 1][d];
        v.z = T[rg * 4 + 2][d];
        v.w = T[rg * 4 + 3][d];
        *(float4*)&dstT[d * NB + rowbase + rg * 4] = v;
    }
}

// ---------------------------------------------------------------------------
// Main: 64x64 tile, 256 threads, 4x4 micro-tile, cp.async double buffer,
// merged accumulator, 5 min : 3 abs per 8 dims (pipe-balanced):
//   min dim : acc += min(u,v)      (FMNMX alu + FADD fma)
//   abs dim : acc -= |u' - v'|     (FADD + FADD.neg-abs, fma pipe)
// out = ex2(P + Q + K_MIN*acc)
// ---------------------------------------------------------------------------
__global__ __launch_bounds__(256, 5) void alcove_main(float* __restrict__ out)
{
    __shared__ float Xs[2][KCH * TILE];   // 2 x 8KB
    __shared__ float Es[2][KCH * TILE];   // 2 x 8KB

    int tid = threadIdx.x;
    int tx  = tid & 15;
    int ty  = tid >> 4;
    int rb  = blockIdx.y * TILE;
    int cb  = blockIdx.x * TILE;

    float acc[4][4];
    #pragma unroll
    for (int i = 0; i < 4; i++)
        #pragma unroll
        for (int j = 0; j < 4; j++) acc[i][j] = 0.0f;

    int fi0 = tid, fi1 = tid + 256;
    int d0 = fi0 >> 4, q0i = fi0 & 15;
    int d1 = fi1 >> 4, q1i = fi1 & 15;

    const float4* gx = (const float4*)g_XT;
    const float4* ge = (const float4*)g_ET;

    unsigned sx0 = (unsigned)__cvta_generic_to_shared(&Xs[0][0]);
    unsigned se0 = (unsigned)__cvta_generic_to_shared(&Es[0][0]);

    auto issue_stage = [&](int kb, int buf) {
        int base = kb * KCH;
        unsigned xb = sx0 + buf * (KCH * TILE * 4);
        unsigned eb = se0 + buf * (KCH * TILE * 4);
        cp16(xb + (d0 * 16 + q0i) * 16, &gx[(base + d0) * (NB/4) + (rb>>2) + q0i]);
        cp16(xb + (d1 * 16 + q1i) * 16, &gx[(base + d1) * (NB/4) + (rb>>2) + q1i]);
        cp16(eb + (d0 * 16 + q0i) * 16, &ge[(base + d0) * (NB/4) + (cb>>2) + q0i]);
        cp16(eb + (d1 * 16 + q1i) * 16, &ge[(base + d1) * (NB/4) + (cb>>2) + q1i]);
        cp_commit();
    };

    issue_stage(0, 0);

    #pragma unroll 1
    for (int kb = 0; kb < NCH; kb++) {
        int buf = kb & 1;
        cp_wait<0>();          // stage kb data landed
        __syncthreads();       // all warps finished reading buf^1
        if (kb + 1 < NCH)
            issue_stage(kb + 1, buf ^ 1);   // overlaps with compute below

        const float* Xb = &Xs[buf][ty * 4];
        const float* Eb = &Es[buf][tx * 4];

        auto mind = [&](int d) {
            float4 xv = *(const float4*)&Xb[d * TILE];
            float4 ev = *(const float4*)&Eb[d * TILE];
            float x[4] = {xv.x, xv.y, xv.z, xv.w};
            #pragma unroll
            for (int i = 0; i < 4; i++) {
                acc[i][0] += fminf(x[i], ev.x);
                acc[i][1] += fminf(x[i], ev.y);
                acc[i][2] += fminf(x[i], ev.z);
                acc[i][3] += fminf(x[i], ev.w);
            }
        };
        auto absd = [&](int d) {
            float4 xv = *(const float4*)&Xb[d * TILE];
            float4 ev = *(const float4*)&Eb[d * TILE];
            float x[4] = {xv.x, xv.y, xv.z, xv.w};
            #pragma unroll
            for (int i = 0; i < 4; i++) {
                acc[i][0] -= fabsf(x[i] - ev.x);
                acc[i][1] -= fabsf(x[i] - ev.y);
                acc[i][2] -= fabsf(x[i] - ev.z);
                acc[i][3] -= fabsf(x[i] - ev.w);
            }
        };

        #pragma unroll
        for (int d8 = 0; d8 < KCH; d8 += 8) {
            mind(d8 + 0);
            mind(d8 + 1);
            absd(d8 + 2);      // d%8 == 2
            mind(d8 + 3);
            mind(d8 + 4);
            absd(d8 + 5);      // d%8 == 5
            mind(d8 + 6);
            absd(d8 + 7);      // d%8 == 7
        }
    }

    // Epilogue: out = ex2(p + q + K_MIN*acc)
    float q0 = g_Q[cb + tx * 4 + 0];
    float q1 = g_Q[cb + tx * 4 + 1];
    float q2 = g_Q[cb + tx * 4 + 2];
    float q3 = g_Q[cb + tx * 4 + 3];
    #pragma unroll
    for (int i = 0; i < 4; i++) {
        int r = rb + ty * 4 + i;
        float p = g_P[r];
        float4 o;
        o.x = ex2(fmaf(K_MIN, acc[i][0], p + q0));
        o.y = ex2(fmaf(K_MIN, acc[i][1], p + q1));
        o.z = ex2(fmaf(K_MIN, acc[i][2], p + q2));
        o.w = ex2(fmaf(K_MIN, acc[i][3], p + q3));
        *(float4*)&out[r * NB + cb + tx * 4] = o;
    }
}

// ---------------------------------------------------------------------------
extern "C" void kernel_launch(void* const* d_in, const int* in_sizes, int n_in,
                              void* d_out, int out_size)
{
    const float* inputs    = (const float*)d_in[0];
    const float* exemplars = (const float*)d_in[1];
    const float* attn      = (const float*)d_in[2];
    float* out = (float*)d_out;

    prep2_kernel<<<128, 256>>>(inputs, exemplars, attn);

    dim3 grid(NB / TILE, NB / TILE);   // 32 x 32 = 1024 tiles
    alcove_main<<<grid, 256>>>(out);
}